// round 7
// baseline (speedup 1.0000x reference)
#include <cuda_runtime.h>

// Problem constants
#define KK 4
#define MM 32
#define DD 2048
#define TT 128
#define TTILE 16          // t-columns per CTA (8 t-pairs; 64B of each 128B line)
#define NTH 1024
#define NTILES 1024       // KK*MM * (TT/TTILE)

typedef unsigned long long u64;

// smem (u64 units): xch 16384 (128KB) + 4 scale tables * 2048 (64KB) = 192KB
#define XCH 16384
#define S1O (XCH)
#define S2O (XCH + 2048)
#define S3O (XCH + 4096)
#define SBO (XCH + 6144)
#define SMEM_U64 (XCH + 8192)
#define SMEM_BYTES (SMEM_U64 * 8)

#define HNORM 0.022097086912079608f   // 1/sqrt(2048), folded per diagonal
#define SGN 0x8000000080000000ULL

// ---- packed f32x2 helpers (sm_103a); lanes = (t, t+1), same d ----
__device__ __forceinline__ u64 addx2(u64 a, u64 b) {
    u64 r; asm("add.rn.f32x2 %0,%1,%2;" : "=l"(r) : "l"(a), "l"(b)); return r;
}
__device__ __forceinline__ u64 subx2(u64 a, u64 b) {
    u64 r; asm("sub.rn.f32x2 %0,%1,%2;" : "=l"(r) : "l"(a), "l"(b)); return r;
}
__device__ __forceinline__ u64 mulx2(u64 a, u64 b) {
    u64 r; asm("mul.rn.f32x2 %0,%1,%2;" : "=l"(r) : "l"(a), "l"(b)); return r;
}
__device__ __forceinline__ u64 pk(float lo, float hi) {
    u64 r; asm("mov.b64 %0,{%1,%2};" : "=l"(r) : "f"(lo), "f"(hi)); return r;
}

#define BFLY(A, B) { u64 _a = (A), _b = (B); (A) = addx2(_a, _b); (B) = subx2(_a, _b); }

// 4 local butterfly stages over the 16-register array (reg-index bits 0..3)
#define LOCAL4(y) \
    { _Pragma("unroll") for (int s = 1; s < 16; s <<= 1) { \
        _Pragma("unroll") for (int j = 0; j < 16; ++j) \
            if ((j & s) == 0) BFLY(y[j], y[j | s]); } }

// cross-lane butterfly over one lane bit; qm = SGN if this thread holds bit=1
#define CROSSL(y, lx, qm) \
    { _Pragma("unroll") for (int i = 0; i < 16; ++i) { \
        u64 _o = __shfl_xor_sync(0xffffffffu, y[i], (lx)); \
        y[i] = addx2(_o, y[i] ^ (qm)); } }

__global__ __launch_bounds__(NTH, 1)
void spinner_main_kernel(const float* __restrict__ z,
                         const float* __restrict__ d1,
                         const float* __restrict__ d2,
                         const float* __restrict__ d3,
                         const float* __restrict__ bia,
                         const float* __restrict__ sldj_in,
                         float* __restrict__ out)
{
    extern __shared__ __align__(16) u64 sm[];
    const int tid = threadIdx.x;
    const int bid = blockIdx.x;

    // ---- extra CTA: sldj ----
    if (bid == NTILES) {
        float* red = (float*)sm;
        float s = 0.f;
        #pragma unroll
        for (int r = 0; r < 2; ++r) {
            int i = tid + r * NTH;
            s += logf(fabsf(d1[i])) + logf(fabsf(d2[i])) + logf(fabsf(d3[i]));
        }
        #pragma unroll
        for (int o = 16; o > 0; o >>= 1) s += __shfl_xor_sync(0xffffffffu, s, o);
        if ((tid & 31) == 0) red[tid >> 5] = s;
        __syncthreads();
        if (tid < 32) {
            float v = red[tid];
            #pragma unroll
            for (int o = 16; o > 0; o >>= 1) v += __shfl_xor_sync(0xffffffffu, v, o);
            if (tid == 0) red[40] = v;
        }
        __syncthreads();
        if (tid < KK * MM)
            out[(size_t)KK * MM * DD * TT + tid] = sldj_in[tid] + red[40];
        return;
    }

    // ---- stage scale tables (duplicated-pair u64, scrambled indices) ----
    #pragma unroll
    for (int r = 0; r < 2; ++r) {
        int e = tid + r * NTH;
        int g1 = e ^ ((e >> 4) & 1) ^ (((e >> 5) & 1) << 1);
        int g2 = e ^ (((e >> 6) & 1) << 1);
        float v1 = d1[e] * HNORM, v2 = d2[e] * HNORM, v3 = d3[e] * HNORM, vb = bia[e];
        sm[S1O + g1] = pk(v1, v1);
        sm[S2O + g2] = pk(v2, v2);
        sm[S3O + g1] = pk(v3, v3);
        sm[SBO + g2] = pk(vb, vb);
    }
    __syncthreads();

    // lane decode: bits0-2 = tp (t-pair), bit3 = l3, bit4 = l4; bits5-9 = W
    const int tp = tid & 7;
    const int l3 = (tid >> 3) & 1;
    const int l4 = (tid >> 4) & 1;
    const int W  = tid >> 5;
    const u64 qm3 = l3 ? SGN : 0ULL;
    const u64 qm4 = l4 ? SGN : 0ULL;

    // phase-1: d = W*64 + l4*32 + l3*16 + r      (owns d bits 0..5 with lanes)
    // phase-2: d = r*128 + l3*64 + W*2 + l4      (owns d bits 6..10 with l3)
    const int base1 = W * 64 + l4 * 32 + l3 * 16;
    const int base2 = l3 * 64 + W * 2 + l4;
    const int c1 = (l3 ^ W) & 1;                  // f(d) low-bit fix, phase-1
    const int c2 = ((W >> 3) ^ l3) & 1;           // f(d) low-bit fix, phase-2
    const int scr1 = l3 + 2 * l4;                 // g1 scramble, phase-1 reads
    const int b2s  = l3 * 64 + 2 * (W ^ l3) + l4; // g2-scrambled phase-2 base

    const int km = bid >> 3;
    const int t0 = (bid & 7) * TTILE;
    const u64* zin  = (const u64*)z  + (size_t)km * (DD * TT / 2) + (t0 >> 1) + tp;
    u64*       zout = (u64*)out      + (size_t)km * (DD * TT / 2) + (t0 >> 1) + tp;

    u64 y[16];

    // ---- load + d1 scale (phase-1) ----
    #pragma unroll
    for (int r = 0; r < 16; ++r)
        y[r] = mulx2(zin[(size_t)(base1 + r) * 64], sm[S1O + base1 + (r ^ scr1)]);

    // ---- H(1) low: bits 0..5 ----
    LOCAL4(y); CROSSL(y, 8, qm3); CROSSL(y, 16, qm4);

    // E1: phase-1 -> phase-2
    #pragma unroll
    for (int r = 0; r < 16; ++r) sm[(base1 + (r ^ c1)) * 8 + tp] = y[r];
    __syncthreads();
    #pragma unroll
    for (int r = 0; r < 16; ++r)
        y[r] = sm[(r * 128 + l3 * 64 + W * 2 + (l4 ^ c2)) * 8 + tp];

    // ---- H(1) high: bits 6..10 ----
    CROSSL(y, 8, qm3); LOCAL4(y);

    // ---- d2 scale (phase-2) ----
    #pragma unroll
    for (int r = 0; r < 16; ++r)
        y[r] = mulx2(y[r], sm[S2O + r * 128 + b2s]);

    // ---- H(2) high: bits 6..10 ----
    LOCAL4(y); CROSSL(y, 8, qm3);

    // E2: phase-2 -> phase-1 (writes this thread's own E1-read slots: no pre-sync)
    #pragma unroll
    for (int r = 0; r < 16; ++r)
        sm[(r * 128 + l3 * 64 + W * 2 + (l4 ^ c2)) * 8 + tp] = y[r];
    __syncthreads();
    #pragma unroll
    for (int r = 0; r < 16; ++r) y[r] = sm[(base1 + (r ^ c1)) * 8 + tp];

    // ---- H(2) low: bits 0..5 ----
    CROSSL(y, 16, qm4); CROSSL(y, 8, qm3); LOCAL4(y);

    // ---- d3 scale (phase-1) ----
    #pragma unroll
    for (int r = 0; r < 16; ++r)
        y[r] = mulx2(y[r], sm[S3O + base1 + (r ^ scr1)]);

    // ---- H(3) low: bits 0..5 ----
    LOCAL4(y); CROSSL(y, 8, qm3); CROSSL(y, 16, qm4);

    // E3: phase-1 -> phase-2 (writes own E2-read slots: no pre-sync)
    #pragma unroll
    for (int r = 0; r < 16; ++r) sm[(base1 + (r ^ c1)) * 8 + tp] = y[r];
    __syncthreads();
    #pragma unroll
    for (int r = 0; r < 16; ++r)
        y[r] = sm[(r * 128 + l3 * 64 + W * 2 + (l4 ^ c2)) * 8 + tp];

    // ---- H(3) high: bits 6..10 ----
    CROSSL(y, 8, qm3); LOCAL4(y);

    // ---- bias + store (phase-2) ----
    #pragma unroll
    for (int r = 0; r < 16; ++r) {
        u64 v = addx2(y[r], sm[SBO + r * 128 + b2s]);
        zout[(size_t)(r * 128 + base2) * 64] = v;
    }
}

extern "C" void kernel_launch(void* const* d_in, const int* in_sizes, int n_in,
                              void* d_out, int out_size)
{
    (void)in_sizes; (void)n_in; (void)out_size;
    const float* z    = (const float*)d_in[0];
    const float* d1   = (const float*)d_in[1];
    const float* d2   = (const float*)d_in[2];
    const float* d3   = (const float*)d_in[3];
    const float* bia  = (const float*)d_in[4];
    const float* sldj = (const float*)d_in[5];
    float* out = (float*)d_out;

    cudaFuncSetAttribute(spinner_main_kernel,
                         cudaFuncAttributeMaxDynamicSharedMemorySize, SMEM_BYTES);

    spinner_main_kernel<<<NTILES + 1, NTH, SMEM_BYTES>>>(
        z, d1, d2, d3, bia, sldj, out);
}

// round 8
// speedup vs baseline: 1.0628x; 1.0628x over previous
#include <cuda_runtime.h>

// Problem constants
#define KK 4
#define MM 32
#define DD 2048
#define TT 128
#define TTILE 16          // t-columns per CTA
#define NTH 512
#define NTILES 1024       // 128 km * 8 t-blocks

typedef unsigned long long u64;

// smem (u64 units): xch 16*1025 + 4 tables * 1024
#define XS 1025
#define XCH_U64 (16 * XS)          // 16400
#define TB1 (XCH_U64)
#define TB2 (XCH_U64 + 1024)
#define TB3 (XCH_U64 + 2048)
#define TBB (XCH_U64 + 3072)
#define SMEM_U64 (XCH_U64 + 4096)  // 20496
#define SMEM_BYTES (SMEM_U64 * 8)  // 163968

#define HNORM 0.022097086912079608f   // 1/sqrt(2048), folded per diagonal

// ---- packed f32x2 helpers (sm_103a); pack = (d, d+32) ----
__device__ __forceinline__ u64 addx2(u64 a, u64 b) {
    u64 r; asm("add.rn.f32x2 %0,%1,%2;" : "=l"(r) : "l"(a), "l"(b)); return r;
}
__device__ __forceinline__ u64 subx2(u64 a, u64 b) {
    u64 r; asm("sub.rn.f32x2 %0,%1,%2;" : "=l"(r) : "l"(a), "l"(b)); return r;
}
__device__ __forceinline__ u64 mulx2(u64 a, u64 b) {
    u64 r; asm("mul.rn.f32x2 %0,%1,%2;" : "=l"(r) : "l"(a), "l"(b)); return r;
}
__device__ __forceinline__ u64 pk(float lo, float hi) {
    u64 r; asm("mov.b64 %0,{%1,%2};" : "=l"(r) : "f"(lo), "f"(hi)); return r;
}
__device__ __forceinline__ void upk(float& lo, float& hi, u64 v) {
    asm("mov.b64 {%0,%1},%2;" : "=f"(lo), "=f"(hi) : "l"(v));
}

#define BFLY(A, B) { u64 _a = (A), _b = (B); (A) = addx2(_a, _b); (B) = subx2(_a, _b); }

// 5 register butterfly stages over the 32-u64 array (index bits 0..4)
#define LOCAL5(y) \
    { _Pragma("unroll") for (int s = 1; s < 32; s <<= 1) { \
        _Pragma("unroll") for (int j = 0; j < 32; ++j) \
            if ((j & s) == 0) BFLY(y[j], y[j | s]); } }

// intra-pack stage (the d5 bit: pair = (d, d+32))
#define INTRA32(y) \
    { _Pragma("unroll") for (int i = 0; i < 32; ++i) { \
        float _lo, _hi; upk(_lo, _hi, y[i]); \
        y[i] = pk(_lo + _hi, _lo - _hi); } }

__global__ __launch_bounds__(NTH, 1)
void spinner_main_kernel(const float* __restrict__ z,
                         const float* __restrict__ d1,
                         const float* __restrict__ d2,
                         const float* __restrict__ d3,
                         const float* __restrict__ bia,
                         const float* __restrict__ sldj_in,
                         float* __restrict__ out)
{
    extern __shared__ __align__(16) u64 sm[];
    const int tid = threadIdx.x;
    const int bid = blockIdx.x;

    // ---- extra CTA: sldj ----
    if (bid == NTILES) {
        float* red = (float*)sm;
        float s = 0.f;
        #pragma unroll
        for (int r = 0; r < 4; ++r) {
            int i = tid + r * NTH;
            s += logf(fabsf(d1[i])) + logf(fabsf(d2[i])) + logf(fabsf(d3[i]));
        }
        #pragma unroll
        for (int o = 16; o > 0; o >>= 1) s += __shfl_xor_sync(0xffffffffu, s, o);
        if ((tid & 31) == 0) red[tid >> 5] = s;
        __syncthreads();
        if (tid < 32) {
            float v = (tid < NTH / 32) ? red[tid] : 0.f;
            #pragma unroll
            for (int o = 16; o > 0; o >>= 1) v += __shfl_xor_sync(0xffffffffu, v, o);
            if (tid == 0) red[40] = v;
        }
        __syncthreads();
        if (tid < KK * MM)
            out[(size_t)KK * MM * DD * TT + tid] = sldj_in[tid] + red[40];
        return;
    }

    // ---- stage packed scale tables: tab[D], D = dlo*32 + dhi ----
    #pragma unroll
    for (int r = 0; r < 2; ++r) {
        int D = tid + r * NTH;
        int dl = D >> 5, dh = D & 31;
        int d  = dh * 64 + dl;          // pair = (d, d+32)
        sm[TB1 + D] = pk(d1[d] * HNORM, d1[d + 32] * HNORM);
        sm[TB2 + D] = pk(d2[d] * HNORM, d2[d + 32] * HNORM);
        sm[TB3 + D] = pk(d3[d] * HNORM, d3[d + 32] * HNORM);
        sm[TBB + D] = pk(bia[d], bia[d + 32]);
    }
    __syncthreads();

    // thread decode: lanes = t(4) + l4(1); warp = w(4)
    const int t   = tid & 15;
    const int l4  = (tid >> 4) & 1;
    const int w   = tid >> 5;           // 0..15
    const int dhi = l4 + 2 * w;         // phase-1 fixed d10..d6  (0..31)
    const int dlo = l4 * 16 + w;        // phase-2 fixed d4..d0   (0..31)

    const int km = bid >> 3;
    const int t0 = (bid & 7) * TTILE;
    const float* zin  = z   + (size_t)km * (DD * TT) + (t0 + t);
    float*       zout = out + (size_t)km * (DD * TT) + (t0 + t);
    u64* xc = sm + t * XS;              // this t-column's exchange buffer

    u64 y[32];

    // ---- load + d1 scale (phase-1: d = dhi*64 + s*32 + r) ----
    {
        const float* zp = zin + (size_t)(dhi * 64) * TT;
        #pragma unroll
        for (int r = 0; r < 32; ++r)
            y[r] = mulx2(pk(zp[(size_t)r * TT], zp[(size_t)(r + 32) * TT]),
                         sm[TB1 + r * 32 + dhi]);
    }

    // ---- FWHT #1 low: d0..d4 (regs) + d5 (pack) ----
    LOCAL5(y); INTRA32(y);

    // E1: phase-1 -> phase-2   (slot D = dlo*32 + dhi)
    #pragma unroll
    for (int r = 0; r < 32; ++r) xc[r * 32 + dhi] = y[r];
    __syncthreads();
    #pragma unroll
    for (int r = 0; r < 32; ++r) y[r] = xc[dlo * 32 + r];

    // ---- FWHT #1 high: d6..d10 (regs) ----
    LOCAL5(y);

    // ---- d2 scale (phase-2) ----
    #pragma unroll
    for (int r = 0; r < 32; ++r)
        y[r] = mulx2(y[r], sm[TB2 + dlo * 32 + r]);

    // ---- FWHT #2 high ----
    LOCAL5(y);

    // E2: phase-2 -> phase-1 (writes own E1-read slots: no pre-sync needed)
    #pragma unroll
    for (int r = 0; r < 32; ++r) xc[dlo * 32 + r] = y[r];
    __syncthreads();
    #pragma unroll
    for (int r = 0; r < 32; ++r) y[r] = xc[r * 32 + dhi];

    // ---- FWHT #2 low ----
    INTRA32(y); LOCAL5(y);

    // ---- d3 scale (phase-1) ----
    #pragma unroll
    for (int r = 0; r < 32; ++r)
        y[r] = mulx2(y[r], sm[TB3 + r * 32 + dhi]);

    // ---- FWHT #3 low ----
    LOCAL5(y); INTRA32(y);

    // E3: phase-1 -> phase-2 (writes own E2-read slots: no pre-sync needed)
    #pragma unroll
    for (int r = 0; r < 32; ++r) xc[r * 32 + dhi] = y[r];
    __syncthreads();
    #pragma unroll
    for (int r = 0; r < 32; ++r) y[r] = xc[dlo * 32 + r];

    // ---- FWHT #3 high ----
    LOCAL5(y);

    // ---- bias + store (phase-2: d = r*64 + s*32 + dlo) ----
    {
        float* zp = zout + (size_t)dlo * TT;
        #pragma unroll
        for (int r = 0; r < 32; ++r) {
            u64 v = addx2(y[r], sm[TBB + dlo * 32 + r]);
            float lo, hi; upk(lo, hi, v);
            zp[(size_t)(r * 64)      * TT] = lo;
            zp[(size_t)(r * 64 + 32) * TT] = hi;
        }
    }
}

extern "C" void kernel_launch(void* const* d_in, const int* in_sizes, int n_in,
                              void* d_out, int out_size)
{
    (void)in_sizes; (void)n_in; (void)out_size;
    const float* z    = (const float*)d_in[0];
    const float* d1   = (const float*)d_in[1];
    const float* d2   = (const float*)d_in[2];
    const float* d3   = (const float*)d_in[3];
    const float* bia  = (const float*)d_in[4];
    const float* sldj = (const float*)d_in[5];
    float* out = (float*)d_out;

    cudaFuncSetAttribute(spinner_main_kernel,
                         cudaFuncAttributeMaxDynamicSharedMemorySize, SMEM_BYTES);

    spinner_main_kernel<<<NTILES + 1, NTH, SMEM_BYTES>>>(
        z, d1, d2, d3, bia, sldj, out);
}